// round 2
// baseline (speedup 1.0000x reference)
#include <cuda_runtime.h>
#include <math.h>

#define BB   2
#define SS   2048
#define DD   1024
#define HH   16
#define HDIM 64
#define MTOT (BB*SS)   // 4096

// Scratch (allocation-free rule: __device__ globals). 4 x 16MB = 64MB.
__device__ float g_q[BB*HH*SS*HDIM];
__device__ float g_k[BB*HH*SS*HDIM];
__device__ float g_v[BB*HH*SS*HDIM];
__device__ float g_ctx[BB*HH*SS*HDIM];

// ---------------------------------------------------------------------------
// Projection GEMM: out = X[M,K] @ W[N,K]^T + b   (M=4096, N=K=1024)
// Output scattered into [B,H,S,HD] layout (g_q / g_k / g_v picked by `which`).
// Tile 64x64, BK=16, 256 threads, 4x4 micro-tile per thread.
// ---------------------------------------------------------------------------
__global__ __launch_bounds__(256) void proj_kernel(
    const float* __restrict__ X, const float* __restrict__ W,
    const float* __restrict__ bias, int which)
{
    __shared__ __align__(16) float As[16][68];   // [k][m], padded
    __shared__ __align__(16) float Bs[16][68];   // [k][n], padded

    float* __restrict__ out = (which == 0) ? g_q : (which == 1) ? g_k : g_v;

    const int tid = threadIdx.x;
    const int tx  = tid & 15;
    const int ty  = tid >> 4;
    const int m0  = blockIdx.y * 64;
    const int n0  = blockIdx.x * 64;

    float acc[4][4] = {};

    const int lr = tid >> 2;   // 0..63 (row within tile for loads)
    const int lc = tid & 3;    // 0..3  (float4 group within BK)

    for (int k0 = 0; k0 < DD; k0 += 16) {
        float4 a = *(const float4*)(X + (size_t)(m0 + lr) * DD + k0 + lc * 4);
        float4 b = *(const float4*)(W + (size_t)(n0 + lr) * DD + k0 + lc * 4);
        As[lc*4+0][lr] = a.x; As[lc*4+1][lr] = a.y; As[lc*4+2][lr] = a.z; As[lc*4+3][lr] = a.w;
        Bs[lc*4+0][lr] = b.x; Bs[lc*4+1][lr] = b.y; Bs[lc*4+2][lr] = b.z; Bs[lc*4+3][lr] = b.w;
        __syncthreads();

        #pragma unroll
        for (int kk = 0; kk < 16; kk++) {
            float4 av4 = *(const float4*)&As[kk][ty * 4];
            float4 bv4 = *(const float4*)&Bs[kk][tx * 4];
            float av[4] = {av4.x, av4.y, av4.z, av4.w};
            float bv[4] = {bv4.x, bv4.y, bv4.z, bv4.w};
            #pragma unroll
            for (int i = 0; i < 4; i++)
                #pragma unroll
                for (int j = 0; j < 4; j++)
                    acc[i][j] += av[i] * bv[j];
        }
        __syncthreads();
    }

    // Epilogue: scatter to [B,H,S,HD]
    const int n  = n0 + tx * 4;          // n..n+3 stay within one head (n0%64==0)
    const int h  = n >> 6;
    const int hd = n & 63;
    float4 bv = *(const float4*)(bias + n);
    #pragma unroll
    for (int i = 0; i < 4; i++) {
        int m = m0 + ty * 4 + i;
        int b = m / SS, s = m - b * SS;
        float4 r;
        r.x = acc[i][0] + bv.x;
        r.y = acc[i][1] + bv.y;
        r.z = acc[i][2] + bv.z;
        r.w = acc[i][3] + bv.w;
        *(float4*)(out + (((size_t)(b * HH + h)) * SS + s) * HDIM + hd) = r;
    }
}

// ---------------------------------------------------------------------------
// Flash attention: per (b, h, 64-row q tile). 256 threads, 4x4 micro-tiles.
// Smem: Qs (transposed [d][row]) + KP (K transposed [d][col], reused for P
// in natural [row][kt] layout) + Vs ([kt][hd]) = 48KB exactly.
// ---------------------------------------------------------------------------
__global__ __launch_bounds__(256) void flash_kernel()
{
    __shared__ __align__(16) float Qs[64][64];
    __shared__ __align__(16) float KP[64][64];
    __shared__ __align__(16) float Vs[64][64];

    const int tid = threadIdx.x;
    const int tx  = tid & 15;
    const int ty  = tid >> 4;
    const int q0  = blockIdx.x * 64;
    const int h   = blockIdx.y;
    const int b   = blockIdx.z;

    const size_t head_off = ((size_t)(b * HH + h)) * SS * HDIM;
    const float* __restrict__ qb = g_q + head_off;
    const float* __restrict__ kb = g_k + head_off;
    const float* __restrict__ vb = g_v + head_off;

    const int lr = tid >> 2;  // 0..63
    const int lg = tid & 3;   // 0..3

    // Load Q tile transposed: Qs[d][row]
    #pragma unroll
    for (int i = 0; i < 4; i++) {
        float4 v = *(const float4*)(qb + (size_t)(q0 + lr) * HDIM + lg * 16 + i * 4);
        Qs[lg*16 + i*4 + 0][lr] = v.x;
        Qs[lg*16 + i*4 + 1][lr] = v.y;
        Qs[lg*16 + i*4 + 2][lr] = v.z;
        Qs[lg*16 + i*4 + 3][lr] = v.w;
    }

    float acc[4][4] = {};
    float mrow[4], lrow[4] = {};
    #pragma unroll
    for (int i = 0; i < 4; i++) mrow[i] = -3.0e38f;

    const float scale = 0.125f;  // 1/sqrt(64)

    for (int kt0 = 0; kt0 < SS; kt0 += 64) {
        __syncthreads();   // prev PV done reading KP/Vs; Q store visible (iter 0)

        // Load K transposed [d][col], V natural [kt][hd]
        #pragma unroll
        for (int i = 0; i < 4; i++) {
            float4 kv = *(const float4*)(kb + (size_t)(kt0 + lr) * HDIM + lg * 16 + i * 4);
            KP[lg*16 + i*4 + 0][lr] = kv.x;
            KP[lg*16 + i*4 + 1][lr] = kv.y;
            KP[lg*16 + i*4 + 2][lr] = kv.z;
            KP[lg*16 + i*4 + 3][lr] = kv.w;
            float4 vv = *(const float4*)(vb + (size_t)(kt0 + lr) * HDIM + lg * 16 + i * 4);
            *(float4*)&Vs[lr][lg*16 + i*4] = vv;
        }
        __syncthreads();

        // S = Q K^T (rows = q, cols = kt)
        float sreg[4][4] = {};
        #pragma unroll 16
        for (int d = 0; d < 64; d++) {
            float4 qa = *(const float4*)&Qs[d][ty * 4];
            float4 ka = *(const float4*)&KP[d][tx * 4];
            float qv[4] = {qa.x, qa.y, qa.z, qa.w};
            float kv[4] = {ka.x, ka.y, ka.z, ka.w};
            #pragma unroll
            for (int i = 0; i < 4; i++)
                #pragma unroll
                for (int j = 0; j < 4; j++)
                    sreg[i][j] += qv[i] * kv[j];
        }
        __syncthreads();   // all KP reads (as K) done before P overwrite

        // Online softmax; stats fully register-resident (replicated across the
        // 16 lanes of each row group, kept consistent by the butterfly reduces)
        #pragma unroll
        for (int i = 0; i < 4; i++) {
            float tm = fmaxf(fmaxf(sreg[i][0], sreg[i][1]),
                             fmaxf(sreg[i][2], sreg[i][3]));
            #pragma unroll
            for (int o = 1; o < 16; o <<= 1)
                tm = fmaxf(tm, __shfl_xor_sync(0xffffffffu, tm, o));
            tm *= scale;
            float mnew = fmaxf(mrow[i], tm);
            float corr = __expf(mrow[i] - mnew);
            mrow[i] = mnew;

            float rs = 0.f;
            #pragma unroll
            for (int j = 0; j < 4; j++) {
                float p = __expf(sreg[i][j] * scale - mnew);
                sreg[i][j] = p;
                rs += p;
            }
            #pragma unroll
            for (int o = 1; o < 16; o <<= 1)
                rs += __shfl_xor_sync(0xffffffffu, rs, o);
            lrow[i] = lrow[i] * corr + rs;

            #pragma unroll
            for (int j = 0; j < 4; j++) acc[i][j] *= corr;

            // store P row naturally: KP[row][kt], conflict-free float4
            float4 pr = {sreg[i][0], sreg[i][1], sreg[i][2], sreg[i][3]};
            *(float4*)&KP[ty * 4 + i][tx * 4] = pr;
        }
        __syncthreads();

        // acc += P @ V
        #pragma unroll 16
        for (int kt = 0; kt < 64; kt++) {
            float pr[4];
            #pragma unroll
            for (int i = 0; i < 4; i++) pr[i] = KP[ty * 4 + i][kt];  // broadcast
            float4 vv4 = *(const float4*)&Vs[kt][tx * 4];
            float vv[4] = {vv4.x, vv4.y, vv4.z, vv4.w};
            #pragma unroll
            for (int i = 0; i < 4; i++)
                #pragma unroll
                for (int j = 0; j < 4; j++)
                    acc[i][j] += pr[i] * vv[j];
        }
    }

    // Normalize and write ctx [B,H,S,HD]
    float* __restrict__ cb = g_ctx + head_off;
    #pragma unroll
    for (int i = 0; i < 4; i++) {
        float inv = 1.0f / lrow[i];
        float4 r;
        r.x = acc[i][0] * inv;
        r.y = acc[i][1] * inv;
        r.z = acc[i][2] * inv;
        r.w = acc[i][3] * inv;
        *(float4*)(cb + (size_t)(q0 + ty * 4 + i) * HDIM + tx * 4) = r;
    }
}

// ---------------------------------------------------------------------------
// Output projection: out[m][n] = sum_k ctx[m][k] * Wo[n][k] + bo[n]
// ctx read from [B,H,S,HD] layout; out is [B,S,D] row-major.
// ---------------------------------------------------------------------------
__global__ __launch_bounds__(256) void oproj_kernel(
    const float* __restrict__ W, const float* __restrict__ bias,
    float* __restrict__ out)
{
    __shared__ __align__(16) float As[16][68];
    __shared__ __align__(16) float Bs[16][68];

    const int tid = threadIdx.x;
    const int tx  = tid & 15;
    const int ty  = tid >> 4;
    const int m0  = blockIdx.y * 64;
    const int n0  = blockIdx.x * 64;

    float acc[4][4] = {};

    const int lr = tid >> 2;
    const int lc = tid & 3;
    const int m  = m0 + lr;
    const int ab = m / SS, as = m - ab * SS;

    for (int k0 = 0; k0 < DD; k0 += 16) {
        int k  = k0 + lc * 4;
        int kh = k >> 6, khd = k & 63;   // BK=16 never crosses a head boundary
        float4 a = *(const float4*)(g_ctx +
                     (((size_t)(ab * HH + kh)) * SS + as) * HDIM + khd);
        float4 bq = *(const float4*)(W + (size_t)(n0 + lr) * DD + k0 + lc * 4);
        As[lc*4+0][lr] = a.x;  As[lc*4+1][lr] = a.y;  As[lc*4+2][lr] = a.z;  As[lc*4+3][lr] = a.w;
        Bs[lc*4+0][lr] = bq.x; Bs[lc*4+1][lr] = bq.y; Bs[lc*4+2][lr] = bq.z; Bs[lc*4+3][lr] = bq.w;
        __syncthreads();

        #pragma unroll
        for (int kk = 0; kk < 16; kk++) {
            float4 av4 = *(const float4*)&As[kk][ty * 4];
            float4 bv4 = *(const float4*)&Bs[kk][tx * 4];
            float av[4] = {av4.x, av4.y, av4.z, av4.w};
            float bv[4] = {bv4.x, bv4.y, bv4.z, bv4.w};
            #pragma unroll
            for (int i = 0; i < 4; i++)
                #pragma unroll
                for (int j = 0; j < 4; j++)
                    acc[i][j] += av[i] * bv[j];
        }
        __syncthreads();
    }

    const int n = n0 + tx * 4;
    float4 bv = *(const float4*)(bias + n);
    #pragma unroll
    for (int i = 0; i < 4; i++) {
        int mm = m0 + ty * 4 + i;
        float4 r;
        r.x = acc[i][0] + bv.x;
        r.y = acc[i][1] + bv.y;
        r.z = acc[i][2] + bv.z;
        r.w = acc[i][3] + bv.w;
        *(float4*)(out + (size_t)mm * DD + n) = r;
    }
}

// ---------------------------------------------------------------------------
extern "C" void kernel_launch(void* const* d_in, const int* in_sizes, int n_in,
                              void* d_out, int out_size)
{
    const float* Q  = (const float*)d_in[0];
    const float* K  = (const float*)d_in[1];
    const float* V  = (const float*)d_in[2];
    const float* Wq = (const float*)d_in[3];
    const float* bq = (const float*)d_in[4];
    const float* Wk = (const float*)d_in[5];
    const float* bk = (const float*)d_in[6];
    const float* Wv = (const float*)d_in[7];
    const float* bv = (const float*)d_in[8];
    const float* Wo = (const float*)d_in[9];
    const float* bo = (const float*)d_in[10];
    float* out = (float*)d_out;

    dim3 pg(DD / 64, MTOT / 64);   // (16, 64)
    proj_kernel<<<pg, 256>>>(Q, Wq, bq, 0);
    proj_kernel<<<pg, 256>>>(K, Wk, bk, 1);
    proj_kernel<<<pg, 256>>>(V, Wv, bv, 2);

    flash_kernel<<<dim3(SS / 64, HH, BB), 256>>>();

    oproj_kernel<<<pg, 256>>>(Wo, bo, out);
}

// round 7
// speedup vs baseline: 1.3229x; 1.3229x over previous
#include <cuda_runtime.h>
#include <cuda_bf16.h>
#include <cstdint>
#include <math.h>

#define BB   2
#define SS   2048
#define DD   1024
#define HH   16
#define HDIM 64
#define MTOT (BB*SS)   // 4096

// ---------------- scratch (__device__ globals; allocation-free rule) -------
// NOTE: these symbols must ONLY be referenced from device code. Passing them
// as kernel arguments from host gives the host shadow address (R5/R6 bug).
__device__ __align__(16) float g_q[BB*HH*SS*HDIM];
__device__ __align__(16) float g_k[BB*HH*SS*HDIM];
__device__ __align__(16) float g_v[BB*HH*SS*HDIM];
__device__ __align__(16) float g_ctx[BB*HH*SS*HDIM];
__device__ __align__(16) __nv_bfloat16 g_xhi[MTOT*DD];
__device__ __align__(16) __nv_bfloat16 g_xlo[MTOT*DD];
__device__ __align__(16) __nv_bfloat16 g_whi[DD*DD];
__device__ __align__(16) __nv_bfloat16 g_wlo[DD*DD];

// ---------------- mma.sync helper ------------------------------------------
__device__ __forceinline__ void mma16816(float* c, const uint32_t* a, const uint32_t* b) {
    asm volatile(
        "mma.sync.aligned.m16n8k16.row.col.f32.bf16.bf16.f32 "
        "{%0,%1,%2,%3},{%4,%5,%6,%7},{%8,%9},{%0,%1,%2,%3};"
        : "+f"(c[0]), "+f"(c[1]), "+f"(c[2]), "+f"(c[3])
        : "r"(a[0]), "r"(a[1]), "r"(a[2]), "r"(a[3]), "r"(b[0]), "r"(b[1]));
}

// ---------------- bf16 split conversion ------------------------------------
__device__ __forceinline__ void split4(float4 v, uint2& hi, uint2& lo) {
    __nv_bfloat16 h0 = __float2bfloat16(v.x), h1 = __float2bfloat16(v.y);
    __nv_bfloat16 h2 = __float2bfloat16(v.z), h3 = __float2bfloat16(v.w);
    __nv_bfloat16 l0 = __float2bfloat16(v.x - __bfloat162float(h0));
    __nv_bfloat16 l1 = __float2bfloat16(v.y - __bfloat162float(h1));
    __nv_bfloat16 l2 = __float2bfloat16(v.z - __bfloat162float(h2));
    __nv_bfloat16 l3 = __float2bfloat16(v.w - __bfloat162float(h3));
    hi.x = ((uint32_t)__bfloat16_as_ushort(h1) << 16) | __bfloat16_as_ushort(h0);
    hi.y = ((uint32_t)__bfloat16_as_ushort(h3) << 16) | __bfloat16_as_ushort(h2);
    lo.x = ((uint32_t)__bfloat16_as_ushort(l1) << 16) | __bfloat16_as_ushort(l0);
    lo.y = ((uint32_t)__bfloat16_as_ushort(l3) << 16) | __bfloat16_as_ushort(l2);
}

// which==0 -> g_xhi/g_xlo (activations), which==1 -> g_whi/g_wlo (weights).
// Destinations referenced DEVICE-SIDE (the R5/R6 host-decay bug fix).
__global__ __launch_bounds__(256) void convert_flat(
    const float* __restrict__ src, int which, int n4)
{
    int i = blockIdx.x * blockDim.x + threadIdx.x;
    if (i >= n4) return;
    __nv_bfloat16* __restrict__ hi = (which == 0) ? g_xhi : g_whi;
    __nv_bfloat16* __restrict__ lo = (which == 0) ? g_xlo : g_wlo;
    uint2 h, l;
    split4(((const float4*)src)[i], h, l);
    ((uint2*)hi)[i] = h;
    ((uint2*)lo)[i] = l;
}

// gather g_ctx [B,H,S,HD] -> row-major [M, D] bf16 hi/lo (device-side symbols)
__global__ __launch_bounds__(256) void convert_ctx(int n4)
{
    int i = blockIdx.x * blockDim.x + threadIdx.x;
    if (i >= n4) return;
    int e  = i * 4;
    int hd = e & 63, s = (e >> 6) & (SS - 1), h = (e >> 17) & (HH - 1), b = e >> 21;
    float4 v = *(const float4*)(g_ctx + e);
    uint2 hp, lp;
    split4(v, hp, lp);
    size_t d = ((size_t)(b * SS + s)) * DD + h * HDIM + hd;
    *(uint2*)(g_xhi + d) = hp;
    *(uint2*)(g_xlo + d) = lp;
}

// ---------------- HMMA GEMM: 128x128 tile, K=1024, 3-pass bf16 split -------
// pass 0: Ahi*Bhi, pass 1: Ahi*Blo, pass 2: Alo*Bhi; fp32 accumulate.
// Smem rows padded to 272B -> conflict-free direct LDS.32 fragment loads per
// the PTX mma.m16n8k16 fragment tables (no ldmatrix, no swizzle).
#define ROWB 272
#define A_OFF 0
#define B_OFF (128*ROWB)
#define SMEM_GEMM (2*128*ROWB)   // 69632

template<int MODE>
__global__ __launch_bounds__(256) void gemm_tc(
    const float* __restrict__ bias, float* __restrict__ outp)
{
    extern __shared__ __align__(16) char sm[];
    const int tid = threadIdx.x, wid = tid >> 5, lid = tid & 31;
    const int n0 = blockIdx.x * 128, m0 = blockIdx.y * 128;
    const int wr = wid & 1;    // M half (64 rows)
    const int wc = wid >> 1;   // N quarter (32 cols)

    float acc[4][4][4] = {};

    const int cp_row = tid >> 4;        // 0..15 (row base, step 16)
    const int cp_g   = tid & 15;        // 16-byte group 0..15

    for (int c = 0; c < 24; c++) {
        const int p  = c >> 3;
        const int kc = (c & 7) * 128;
        const __nv_bfloat16* __restrict__ As = (p < 2)  ? g_xhi : g_xlo;
        const __nv_bfloat16* __restrict__ Bs = (p == 1) ? g_wlo : g_whi;

        __syncthreads();
        #pragma unroll
        for (int i = 0; i < 8; i++) {
            int row = cp_row + i * 16;
            *(uint4*)(sm + A_OFF + row * ROWB + cp_g * 16) =
                *(const uint4*)(As + (size_t)(m0 + row) * DD + kc + cp_g * 8);
            *(uint4*)(sm + B_OFF + row * ROWB + cp_g * 16) =
                *(const uint4*)(Bs + (size_t)(n0 + row) * DD + kc + cp_g * 8);
        }
        __syncthreads();

        #pragma unroll
        for (int st = 0; st < 8; st++) {
            const int kbyte = st * 32 + (lid & 3) * 4;
            uint32_t af[4][4], bf[4][2];
            #pragma unroll
            for (int mt = 0; mt < 4; mt++) {
                const char* base = sm + A_OFF +
                    (wr * 64 + mt * 16 + (lid >> 2)) * ROWB + kbyte;
                af[mt][0] = *(const uint32_t*)(base);
                af[mt][1] = *(const uint32_t*)(base + 8 * ROWB);
                af[mt][2] = *(const uint32_t*)(base + 16);
                af[mt][3] = *(const uint32_t*)(base + 8 * ROWB + 16);
            }
            #pragma unroll
            for (int nt = 0; nt < 4; nt++) {
                const char* base = sm + B_OFF +
                    (wc * 32 + nt * 8 + (lid >> 2)) * ROWB + kbyte;
                bf[nt][0] = *(const uint32_t*)(base);
                bf[nt][1] = *(const uint32_t*)(base + 16);
            }
            #pragma unroll
            for (int mt = 0; mt < 4; mt++)
                #pragma unroll
                for (int nt = 0; nt < 4; nt++)
                    mma16816(acc[mt][nt], af[mt], bf[nt]);
        }
    }

    // epilogue: bias + scatter
    #pragma unroll
    for (int mt = 0; mt < 4; mt++) {
        #pragma unroll
        for (int nt = 0; nt < 4; nt++) {
            int col = n0 + wc * 32 + nt * 8 + (lid & 3) * 2;
            float2 bv = *(const float2*)(bias + col);
            int r0 = m0 + wr * 64 + mt * 16 + (lid >> 2);
            #pragma unroll
            for (int half = 0; half < 2; half++) {
                int r = r0 + half * 8;
                float2 o;
                o.x = acc[mt][nt][half * 2 + 0] + bv.x;
                o.y = acc[mt][nt][half * 2 + 1] + bv.y;
                if (MODE == 3) {
                    *(float2*)(outp + (size_t)r * DD + col) = o;
                } else {
                    float* dst = (MODE == 0) ? g_q : (MODE == 1) ? g_k : g_v;
                    int b = r >> 11, s = r & (SS - 1);
                    int h = col >> 6, hd = col & 63;
                    *(float2*)(dst + (((size_t)(b * HH + h)) * SS + s) * HDIM + hd) = o;
                }
            }
        }
    }
}

// ---------------------------------------------------------------------------
// Flash attention (unchanged, proven in R2): per (b, h, 64-row q tile).
// ---------------------------------------------------------------------------
__global__ __launch_bounds__(256) void flash_kernel()
{
    __shared__ __align__(16) float Qs[64][64];
    __shared__ __align__(16) float KP[64][64];
    __shared__ __align__(16) float Vs[64][64];

    const int tid = threadIdx.x;
    const int tx  = tid & 15;
    const int ty  = tid >> 4;
    const int q0  = blockIdx.x * 64;
    const int h   = blockIdx.y;
    const int b   = blockIdx.z;

    const size_t head_off = ((size_t)(b * HH + h)) * SS * HDIM;
    const float* __restrict__ qb = g_q + head_off;
    const float* __restrict__ kb = g_k + head_off;
    const float* __restrict__ vb = g_v + head_off;

    const int lr = tid >> 2;
    const int lg = tid & 3;

    #pragma unroll
    for (int i = 0; i < 4; i++) {
        float4 v = *(const float4*)(qb + (size_t)(q0 + lr) * HDIM + lg * 16 + i * 4);
        Qs[lg*16 + i*4 + 0][lr] = v.x;
        Qs[lg*16 + i*4 + 1][lr] = v.y;
        Qs[lg*16 + i*4 + 2][lr] = v.z;
        Qs[lg*16 + i*4 + 3][lr] = v.w;
    }

    float acc[4][4] = {};
    float mrow[4], lrow[4] = {};
    #pragma unroll
    for (int i = 0; i < 4; i++) mrow[i] = -3.0e38f;

    const float scale = 0.125f;

    for (int kt0 = 0; kt0 < SS; kt0 += 64) {
        __syncthreads();

        #pragma unroll
        for (int i = 0; i < 4; i++) {
            float4 kv = *(const float4*)(kb + (size_t)(kt0 + lr) * HDIM + lg * 16 + i * 4);
            KP[lg*16 + i*4 + 0][lr] = kv.x;
            KP[lg*16 + i*4 + 1][lr] = kv.y;
            KP[lg*16 + i*4 + 2][lr] = kv.z;
            KP[lg*16 + i*4 + 3][lr] = kv.w;
            float4 vv = *(const float4*)(vb + (size_t)(kt0 + lr) * HDIM + lg * 16 + i * 4);
            *(float4*)&Vs[lr][lg*16 + i*4] = vv;
        }
        __syncthreads();

        float sreg[4][4] = {};
        #pragma unroll 16
        for (int d = 0; d < 64; d++) {
            float4 qa = *(const float4*)&Qs[d][ty * 4];
            float4 ka = *(const float4*)&KP[d][tx * 4];
            float qv[4] = {qa.x, qa.y, qa.z, qa.w};
            float kv[4] = {ka.x, ka.y, ka.z, ka.w};
            #pragma unroll
            for (int i = 0; i < 4; i++)
                #pragma unroll
                for (int j = 0; j < 4; j++)
                    sreg[i][j] += qv[i] * kv[j];
        }
        __syncthreads();

        #pragma unroll
        for (int i = 0; i < 4; i++) {
            float tm = fmaxf(fmaxf(sreg[i][0], sreg[i][1]),
                             fmaxf(sreg[i][2], sreg[i][3]));
            #pragma unroll
            for (int o = 1; o < 16; o <<= 1)
                tm = fmaxf(tm, __shfl_xor_sync(0xffffffffu, tm, o));
            tm *= scale;
            float mnew = fmaxf(mrow[i], tm);
            float corr = __expf(mrow[i] - mnew);
            mrow[i] = mnew;

            float rs = 0.f;
            #pragma unroll
            for (int j = 0; j < 4; j++) {
                float p = __expf(sreg[i][j] * scale - mnew);
                sreg[i][j] = p;
                rs += p;
            }
            #pragma unroll
            for (int o = 1; o < 16; o <<= 1)
                rs += __shfl_xor_sync(0xffffffffu, rs, o);
            lrow[i] = lrow[i] * corr + rs;

            #pragma unroll
            for (int j = 0; j < 4; j++) acc[i][j] *= corr;

            float4 pr = {sreg[i][0], sreg[i][1], sreg[i][2], sreg[i][3]};
            *(float4*)&KP[ty * 4 + i][tx * 4] = pr;
        }
        __syncthreads();

        #pragma unroll 16
        for (int kt = 0; kt < 64; kt++) {
            float pr[4];
            #pragma unroll
            for (int i = 0; i < 4; i++) pr[i] = KP[ty * 4 + i][kt];
            float4 vv4 = *(const float4*)&Vs[kt][tx * 4];
            float vv[4] = {vv4.x, vv4.y, vv4.z, vv4.w};
            #pragma unroll
            for (int i = 0; i < 4; i++)
                #pragma unroll
                for (int j = 0; j < 4; j++)
                    acc[i][j] += pr[i] * vv[j];
        }
    }

    float* __restrict__ cb = g_ctx + head_off;
    #pragma unroll
    for (int i = 0; i < 4; i++) {
        float inv = 1.0f / lrow[i];
        float4 r;
        r.x = acc[i][0] * inv;
        r.y = acc[i][1] * inv;
        r.z = acc[i][2] * inv;
        r.w = acc[i][3] * inv;
        *(float4*)(cb + (size_t)(q0 + ty * 4 + i) * HDIM + tx * 4) = r;
    }
}

// ---------------------------------------------------------------------------
extern "C" void kernel_launch(void* const* d_in, const int* in_sizes, int n_in,
                              void* d_out, int out_size)
{
    const float* Q  = (const float*)d_in[0];
    const float* K  = (const float*)d_in[1];
    const float* V  = (const float*)d_in[2];
    const float* Wq = (const float*)d_in[3];
    const float* bq = (const float*)d_in[4];
    const float* Wk = (const float*)d_in[5];
    const float* bk = (const float*)d_in[6];
    const float* Wv = (const float*)d_in[7];
    const float* bv = (const float*)d_in[8];
    const float* Wo = (const float*)d_in[9];
    const float* bo = (const float*)d_in[10];
    float* out = (float*)d_out;

    cudaFuncSetAttribute(gemm_tc<0>, cudaFuncAttributeMaxDynamicSharedMemorySize, SMEM_GEMM);
    cudaFuncSetAttribute(gemm_tc<1>, cudaFuncAttributeMaxDynamicSharedMemorySize, SMEM_GEMM);
    cudaFuncSetAttribute(gemm_tc<2>, cudaFuncAttributeMaxDynamicSharedMemorySize, SMEM_GEMM);
    cudaFuncSetAttribute(gemm_tc<3>, cudaFuncAttributeMaxDynamicSharedMemorySize, SMEM_GEMM);

    const int x4 = MTOT * DD / 4;   // activations: 1048576 float4 groups
    const int w4 = DD * DD / 4;     // weights:      262144 float4 groups
    dim3 gg(DD / 128, MTOT / 128);  // (8, 32)

    convert_flat<<<x4 / 256, 256>>>(Q, 0, x4);
    convert_flat<<<w4 / 256, 256>>>(Wq, 1, w4);
    gemm_tc<0><<<gg, 256, SMEM_GEMM>>>(bq, nullptr);

    convert_flat<<<x4 / 256, 256>>>(K, 0, x4);
    convert_flat<<<w4 / 256, 256>>>(Wk, 1, w4);
    gemm_tc<1><<<gg, 256, SMEM_GEMM>>>(bk, nullptr);

    convert_flat<<<x4 / 256, 256>>>(V, 0, x4);
    convert_flat<<<w4 / 256, 256>>>(Wv, 1, w4);
    gemm_tc<2><<<gg, 256, SMEM_GEMM>>>(bv, nullptr);

    flash_kernel<<<dim3(SS / 64, HH, BB), 256>>>();

    convert_ctx<<<x4 / 256, 256>>>(x4);
    convert_flat<<<w4 / 256, 256>>>(Wo, 1, w4);
    gemm_tc<3><<<gg, 256, SMEM_GEMM>>>(bo, out);
}

// round 9
// speedup vs baseline: 2.0998x; 1.5873x over previous
#include <cuda_runtime.h>
#include <cuda_bf16.h>
#include <cstdint>
#include <math.h>

#define BB   2
#define SS   2048
#define DD   1024
#define HH   16
#define HDIM 64
#define MTOT (BB*SS)   // 4096

// ---------------- scratch (__device__ globals; device-side refs ONLY) ------
__device__ __align__(16) __nv_bfloat16 g_qhi[BB*HH*SS*HDIM];
__device__ __align__(16) __nv_bfloat16 g_qlo[BB*HH*SS*HDIM];
__device__ __align__(16) __nv_bfloat16 g_khi[BB*HH*SS*HDIM];
__device__ __align__(16) __nv_bfloat16 g_klo[BB*HH*SS*HDIM];
__device__ __align__(16) __nv_bfloat16 g_vhi[BB*HH*SS*HDIM];
__device__ __align__(16) __nv_bfloat16 g_vlo[BB*HH*SS*HDIM];
__device__ __align__(16) __nv_bfloat16 g_xhi[MTOT*DD];
__device__ __align__(16) __nv_bfloat16 g_xlo[MTOT*DD];
__device__ __align__(16) __nv_bfloat16 g_whi[DD*DD];
__device__ __align__(16) __nv_bfloat16 g_wlo[DD*DD];

// ---------------- helpers ---------------------------------------------------
__device__ __forceinline__ void mma16816(float* c, const uint32_t* a, const uint32_t* b) {
    asm volatile(
        "mma.sync.aligned.m16n8k16.row.col.f32.bf16.bf16.f32 "
        "{%0,%1,%2,%3},{%4,%5,%6,%7},{%8,%9},{%0,%1,%2,%3};"
        : "+f"(c[0]), "+f"(c[1]), "+f"(c[2]), "+f"(c[3])
        : "r"(a[0]), "r"(a[1]), "r"(a[2]), "r"(a[3]), "r"(b[0]), "r"(b[1]));
}

// pack two floats -> bf16x2 (x in low half, y in high half)
__device__ __forceinline__ uint32_t pack_bf16x2(float lo, float hi) {
    uint32_t d;
    asm("cvt.rn.bf16x2.f32 %0, %1, %2;" : "=r"(d) : "f"(hi), "f"(lo));
    return d;
}
__device__ __forceinline__ void split_pair(float x, float y, uint32_t& ph, uint32_t& pl) {
    ph = pack_bf16x2(x, y);
    float tx = __uint_as_float(ph << 16);
    float ty = __uint_as_float(ph & 0xFFFF0000u);
    pl = pack_bf16x2(x - tx, y - ty);
}

// fast 2^f via FMA (no MUFU). f <= ~1, clamped at -80.
__device__ __forceinline__ float fast_exp2(float f) {
    f = fmaxf(f, -80.0f);
    float t2 = f + 12582912.0f;            // rint(f) in low mantissa bits
    float r  = f - (t2 - 12582912.0f);     // r in [-0.5, 0.5]
    float p  = 1.0f + r * (0.69314718f + r * (0.24022651f +
                   r * (0.05550411f + r * 0.00961813f)));
    uint32_t eb = (__float_as_uint(t2) << 23) - (0x4B400000u << 23);
    return __uint_as_float(__float_as_uint(p) + eb);
}

// ---------------- bf16 split conversion (inputs/weights) -------------------
__device__ __forceinline__ void split4(float4 v, uint2& hi, uint2& lo) {
    __nv_bfloat16 h0 = __float2bfloat16(v.x), h1 = __float2bfloat16(v.y);
    __nv_bfloat16 h2 = __float2bfloat16(v.z), h3 = __float2bfloat16(v.w);
    __nv_bfloat16 l0 = __float2bfloat16(v.x - __bfloat162float(h0));
    __nv_bfloat16 l1 = __float2bfloat16(v.y - __bfloat162float(h1));
    __nv_bfloat16 l2 = __float2bfloat16(v.z - __bfloat162float(h2));
    __nv_bfloat16 l3 = __float2bfloat16(v.w - __bfloat162float(h3));
    hi.x = ((uint32_t)__bfloat16_as_ushort(h1) << 16) | __bfloat16_as_ushort(h0);
    hi.y = ((uint32_t)__bfloat16_as_ushort(h3) << 16) | __bfloat16_as_ushort(h2);
    lo.x = ((uint32_t)__bfloat16_as_ushort(l1) << 16) | __bfloat16_as_ushort(l0);
    lo.y = ((uint32_t)__bfloat16_as_ushort(l3) << 16) | __bfloat16_as_ushort(l2);
}

__global__ __launch_bounds__(256) void convert_flat(
    const float* __restrict__ src, int which, int n4)
{
    int i = blockIdx.x * blockDim.x + threadIdx.x;
    if (i >= n4) return;
    __nv_bfloat16* __restrict__ hi = (which == 0) ? g_xhi : g_whi;
    __nv_bfloat16* __restrict__ lo = (which == 0) ? g_xlo : g_wlo;
    uint2 h, l;
    split4(((const float4*)src)[i], h, l);
    ((uint2*)hi)[i] = h;
    ((uint2*)lo)[i] = l;
}

// ---------------- HMMA GEMM (proven R7 core): 128x128 tile, 3-pass split ---
#define ROWB 272
#define A_OFF 0
#define B_OFF (128*ROWB)
#define SMEM_GEMM (2*128*ROWB)   // 69632

template<int MODE>
__global__ __launch_bounds__(256) void gemm_tc(
    const float* __restrict__ bias, float* __restrict__ outp)
{
    extern __shared__ __align__(16) char sm[];
    const int tid = threadIdx.x, wid = tid >> 5, lid = tid & 31;
    const int n0 = blockIdx.x * 128, m0 = blockIdx.y * 128;
    const int wr = wid & 1;
    const int wc = wid >> 1;

    float acc[4][4][4] = {};

    const int cp_row = tid >> 4;
    const int cp_g   = tid & 15;

    for (int c = 0; c < 24; c++) {
        const int p  = c >> 3;
        const int kc = (c & 7) * 128;
        const __nv_bfloat16* __restrict__ As = (p < 2)  ? g_xhi : g_xlo;
        const __nv_bfloat16* __restrict__ Bs = (p == 1) ? g_wlo : g_whi;

        __syncthreads();
        #pragma unroll
        for (int i = 0; i < 8; i++) {
            int row = cp_row + i * 16;
            *(uint4*)(sm + A_OFF + row * ROWB + cp_g * 16) =
                *(const uint4*)(As + (size_t)(m0 + row) * DD + kc + cp_g * 8);
            *(uint4*)(sm + B_OFF + row * ROWB + cp_g * 16) =
                *(const uint4*)(Bs + (size_t)(n0 + row) * DD + kc + cp_g * 8);
        }
        __syncthreads();

        #pragma unroll
        for (int st = 0; st < 8; st++) {
            const int kbyte = st * 32 + (lid & 3) * 4;
            uint32_t af[4][4], bf[4][2];
            #pragma unroll
            for (int mt = 0; mt < 4; mt++) {
                const char* base = sm + A_OFF +
                    (wr * 64 + mt * 16 + (lid >> 2)) * ROWB + kbyte;
                af[mt][0] = *(const uint32_t*)(base);
                af[mt][1] = *(const uint32_t*)(base + 8 * ROWB);
                af[mt][2] = *(const uint32_t*)(base + 16);
                af[mt][3] = *(const uint32_t*)(base + 8 * ROWB + 16);
            }
            #pragma unroll
            for (int nt = 0; nt < 4; nt++) {
                const char* base = sm + B_OFF +
                    (wc * 32 + nt * 8 + (lid >> 2)) * ROWB + kbyte;
                bf[nt][0] = *(const uint32_t*)(base);
                bf[nt][1] = *(const uint32_t*)(base + 16);
            }
            #pragma unroll
            for (int mt = 0; mt < 4; mt++)
                #pragma unroll
                for (int nt = 0; nt < 4; nt++)
                    mma16816(acc[mt][nt], af[mt], bf[nt]);
        }
    }

    #pragma unroll
    for (int mt = 0; mt < 4; mt++) {
        #pragma unroll
        for (int nt = 0; nt < 4; nt++) {
            int col = n0 + wc * 32 + nt * 8 + (lid & 3) * 2;
            float2 bv = *(const float2*)(bias + col);
            int r0 = m0 + wr * 64 + mt * 16 + (lid >> 2);
            #pragma unroll
            for (int half = 0; half < 2; half++) {
                int r = r0 + half * 8;
                float ox = acc[mt][nt][half * 2 + 0] + bv.x;
                float oy = acc[mt][nt][half * 2 + 1] + bv.y;
                if (MODE == 3) {
                    float2 o = {ox, oy};
                    *(float2*)(outp + (size_t)r * DD + col) = o;
                } else {
                    __nv_bfloat16* dh = (MODE == 0) ? g_qhi : (MODE == 1) ? g_khi : g_vhi;
                    __nv_bfloat16* dl = (MODE == 0) ? g_qlo : (MODE == 1) ? g_klo : g_vlo;
                    int b = r >> 11, s = r & (SS - 1);
                    int hh = col >> 6, hd = col & 63;
                    size_t off = (((size_t)(b * HH + hh)) * SS + s) * HDIM + hd;
                    uint32_t ph, pl;
                    split_pair(ox, oy, ph, pl);
                    *(uint32_t*)(dh + off) = ph;
                    *(uint32_t*)(dl + off) = pl;
                }
            }
        }
    }
}

// ---------------- flash attention on mma.sync ------------------------------
#define QROWB 144
#define VROWB 272
#define OFF_QHI 0
#define OFF_QLO 18432
#define OFF_KHI 36864
#define OFF_KLO 55296
#define OFF_VHI 73728
#define OFF_VLO 91136
#define OFF_PHI 108544
#define OFF_PLO 143360
#define SMEM_FLASH 178176

__device__ __forceinline__ void s_pass(
    float sf[16][4], const uint32_t a[4][4], const char* kb, int lid)
{
    #pragma unroll
    for (int nt = 0; nt < 16; nt++) {
        #pragma unroll
        for (int ks = 0; ks < 4; ks++) {
            const char* p = kb + (nt * 8 + (lid >> 2)) * QROWB + ks * 32 + (lid & 3) * 4;
            uint32_t bf[2] = { *(const uint32_t*)p, *(const uint32_t*)(p + 16) };
            mma16816(sf[nt], a[ks], bf);
        }
    }
}

__device__ __forceinline__ void pv_pass(
    float acc[8][4], const char* pbase, const char* vb, int lid)
{
    uint32_t aP[8][4];
    const int rb = (lid >> 2) * VROWB + (lid & 3) * 4;
    #pragma unroll
    for (int ks = 0; ks < 8; ks++) {
        const char* p = pbase + rb + ks * 32;
        aP[ks][0] = *(const uint32_t*)(p);
        aP[ks][1] = *(const uint32_t*)(p + 8 * VROWB);
        aP[ks][2] = *(const uint32_t*)(p + 16);
        aP[ks][3] = *(const uint32_t*)(p + 8 * VROWB + 16);
    }
    #pragma unroll
    for (int nt = 0; nt < 8; nt++) {
        #pragma unroll
        for (int ks = 0; ks < 8; ks++) {
            const char* p = vb + (nt * 8 + (lid >> 2)) * VROWB + ks * 32 + (lid & 3) * 4;
            uint32_t bf[2] = { *(const uint32_t*)p, *(const uint32_t*)(p + 16) };
            mma16816(acc[nt], aP[ks], bf);
        }
    }
}

__global__ __launch_bounds__(256, 1) void flash_mma()
{
    extern __shared__ __align__(16) char sm[];
    const int tid = threadIdx.x, wid = tid >> 5, lid = tid & 31;
    const int q0 = blockIdx.x * 128, h = blockIdx.y, b = blockIdx.z;
    const size_t base = ((size_t)(b * HH + h)) * SS * HDIM;
    const float cf = 0.18033688f;   // 0.125 * log2(e)

    // Q tile 128x64 hi/lo -> smem. FIX (R8 NaN): uint4 per 8-elem group ->
    // full 128B row (R8 loaded uint2 -> only half the row, garbage upper half).
    #pragma unroll
    for (int i = 0; i < 4; i++) {
        int idx = tid + i * 256, row = idx >> 3, g = idx & 7;
        size_t src = base + (size_t)(q0 + row) * HDIM + g * 8;
        *(uint4*)(sm + OFF_QHI + row * QROWB + g * 16) = *(const uint4*)(g_qhi + src);
        *(uint4*)(sm + OFF_QLO + row * QROWB + g * 16) = *(const uint4*)(g_qlo + src);
    }
    __syncthreads();

    uint32_t aQh[4][4];
    const int qrb = (wid * 16 + (lid >> 2)) * QROWB + (lid & 3) * 4;
    #pragma unroll
    for (int ks = 0; ks < 4; ks++) {
        const char* p = sm + OFF_QHI + qrb + ks * 32;
        aQh[ks][0] = *(const uint32_t*)(p);
        aQh[ks][1] = *(const uint32_t*)(p + 8 * QROWB);
        aQh[ks][2] = *(const uint32_t*)(p + 16);
        aQh[ks][3] = *(const uint32_t*)(p + 8 * QROWB + 16);
    }

    float acc[8][4] = {};
    float mrow[2] = {-1e30f, -1e30f}, lrow[2] = {0.f, 0.f};

    for (int kt0 = 0; kt0 < SS; kt0 += 128) {
        __syncthreads();

        // K chunk (hi/lo), full rows via uint4 (same fix as Q)
        #pragma unroll
        for (int i = 0; i < 4; i++) {
            int idx = tid + i * 256, row = idx >> 3, g = idx & 7;
            size_t src = base + (size_t)(kt0 + row) * HDIM + g * 8;
            *(uint4*)(sm + OFF_KHI + row * QROWB + g * 16) = *(const uint4*)(g_khi + src);
            *(uint4*)(sm + OFF_KLO + row * QROWB + g * 16) = *(const uint4*)(g_klo + src);
        }
        // V chunk transposed (hi/lo)
        #pragma unroll
        for (int i = 0; i < 8; i++) {
            int idx = tid + i * 256, kt = idx >> 4, g = idx & 15;
            size_t src = base + (size_t)(kt0 + kt) * HDIM + g * 4;
            uint2 vh = *(const uint2*)(g_vhi + src);
            uint2 vl = *(const uint2*)(g_vlo + src);
            #pragma unroll
            for (int j = 0; j < 4; j++) {
                uint16_t hv = (j < 2) ? (uint16_t)(vh.x >> (j * 16))
                                      : (uint16_t)(vh.y >> ((j - 2) * 16));
                uint16_t lv = (j < 2) ? (uint16_t)(vl.x >> (j * 16))
                                      : (uint16_t)(vl.y >> ((j - 2) * 16));
                *(uint16_t*)(sm + OFF_VHI + (g * 4 + j) * VROWB + kt * 2) = hv;
                *(uint16_t*)(sm + OFF_VLO + (g * 4 + j) * VROWB + kt * 2) = lv;
            }
        }
        __syncthreads();

        // S = Q K^T (3-pass split)
        float sf[16][4];
        #pragma unroll
        for (int nt = 0; nt < 16; nt++)
            sf[nt][0] = sf[nt][1] = sf[nt][2] = sf[nt][3] = 0.f;

        s_pass(sf, aQh, sm + OFF_KHI, lid);
        s_pass(sf, aQh, sm + OFF_KLO, lid);
        {
            uint32_t aQl[4][4];
            #pragma unroll
            for (int ks = 0; ks < 4; ks++) {
                const char* p = sm + OFF_QLO + qrb + ks * 32;
                aQl[ks][0] = *(const uint32_t*)(p);
                aQl[ks][1] = *(const uint32_t*)(p + 8 * QROWB);
                aQl[ks][2] = *(const uint32_t*)(p + 16);
                aQl[ks][3] = *(const uint32_t*)(p + 8 * QROWB + 16);
            }
            s_pass(sf, aQl, sm + OFF_KHI, lid);
        }

        // online softmax (rows lid>>2 and +8; quad shfl reduce over lane bits 0-1)
        float corr[2];
        #pragma unroll
        for (int half = 0; half < 2; half++) {
            const int v0 = half * 2, v1 = half * 2 + 1;
            float tm = -1e30f;
            #pragma unroll
            for (int nt = 0; nt < 16; nt++)
                tm = fmaxf(tm, fmaxf(sf[nt][v0], sf[nt][v1]));
            tm = fmaxf(tm, __shfl_xor_sync(0xffffffffu, tm, 1));
            tm = fmaxf(tm, __shfl_xor_sync(0xffffffffu, tm, 2));
            float mn = fmaxf(mrow[half], tm * cf);
            corr[half] = fast_exp2(mrow[half] - mn);
            mrow[half] = mn;
            float sum = 0.f;
            #pragma unroll
            for (int nt = 0; nt < 16; nt++) {
                float p0 = fast_exp2(fmaf(sf[nt][v0], cf, -mn));
                float p1 = fast_exp2(fmaf(sf[nt][v1], cf, -mn));
                sf[nt][v0] = p0; sf[nt][v1] = p1;
                sum += p0 + p1;
            }
            sum += __shfl_xor_sync(0xffffffffu, sum, 1);
            sum += __shfl_xor_sync(0xffffffffu, sum, 2);
            lrow[half] = lrow[half] * corr[half] + sum;
        }
        #pragma unroll
        for (int nt = 0; nt < 8; nt++) {
            acc[nt][0] *= corr[0]; acc[nt][1] *= corr[0];
            acc[nt][2] *= corr[1]; acc[nt][3] *= corr[1];
        }

        // store P hi/lo (own-warp strip; only warp-local sync needed)
        const int pr0 = (wid * 16 + (lid >> 2)) * VROWB;
        const int pcb = 4 * (lid & 3);
        #pragma unroll
        for (int nt = 0; nt < 16; nt++) {
            int cb = nt * 16 + pcb;
            uint32_t ph, pl;
            split_pair(sf[nt][0], sf[nt][1], ph, pl);
            *(uint32_t*)(sm + OFF_PHI + pr0 + cb) = ph;
            *(uint32_t*)(sm + OFF_PLO + pr0 + cb) = pl;
            split_pair(sf[nt][2], sf[nt][3], ph, pl);
            *(uint32_t*)(sm + OFF_PHI + pr0 + 8 * VROWB + cb) = ph;
            *(uint32_t*)(sm + OFF_PLO + pr0 + 8 * VROWB + cb) = pl;
        }
        __syncwarp();

        // acc += P @ V (3-pass split)
        const char* pwhi = sm + OFF_PHI + wid * 16 * VROWB;
        const char* pwlo = sm + OFF_PLO + wid * 16 * VROWB;
        pv_pass(acc, pwhi, sm + OFF_VHI, lid);
        pv_pass(acc, pwhi, sm + OFF_VLO, lid);
        pv_pass(acc, pwlo, sm + OFF_VHI, lid);
    }

    // epilogue: normalize, split, write ctx hi/lo row-major [M, D]
    float inv0 = 1.0f / lrow[0], inv1 = 1.0f / lrow[1];
    int r0 = q0 + wid * 16 + (lid >> 2);
    size_t m0 = (size_t)(b * SS + r0) * DD + h * HDIM;
    #pragma unroll
    for (int nt = 0; nt < 8; nt++) {
        int d = nt * 8 + 2 * (lid & 3);
        uint32_t ph, pl;
        split_pair(acc[nt][0] * inv0, acc[nt][1] * inv0, ph, pl);
        *(uint32_t*)(g_xhi + m0 + d) = ph;
        *(uint32_t*)(g_xlo + m0 + d) = pl;
        split_pair(acc[nt][2] * inv1, acc[nt][3] * inv1, ph, pl);
        *(uint32_t*)(g_xhi + m0 + 8 * DD + d) = ph;
        *(uint32_t*)(g_xlo + m0 + 8 * DD + d) = pl;
    }
}

// ---------------------------------------------------------------------------
extern "C" void kernel_launch(void* const* d_in, const int* in_sizes, int n_in,
                              void* d_out, int out_size)
{
    const float* Q  = (const float*)d_in[0];
    const float* K  = (const float*)d_in[1];
    const float* V  = (const float*)d_in[2];
    const float* Wq = (const float*)d_in[3];
    const float* bq = (const float*)d_in[4];
    const float* Wk = (const float*)d_in[5];
    const float* bk = (const float*)d_in[6];
    const float* Wv = (const float*)d_in[7];
    const float* bv = (const float*)d_in[8];
    const float* Wo = (const float*)d_in[9];
    const float* bo = (const float*)d_in[10];
    float* out = (float*)d_out;

    cudaFuncSetAttribute(gemm_tc<0>, cudaFuncAttributeMaxDynamicSharedMemorySize, SMEM_GEMM);
    cudaFuncSetAttribute(gemm_tc<1>, cudaFuncAttributeMaxDynamicSharedMemorySize, SMEM_GEMM);
    cudaFuncSetAttribute(gemm_tc<2>, cudaFuncAttributeMaxDynamicSharedMemorySize, SMEM_GEMM);
    cudaFuncSetAttribute(gemm_tc<3>, cudaFuncAttributeMaxDynamicSharedMemorySize, SMEM_GEMM);
    cudaFuncSetAttribute(flash_mma,  cudaFuncAttributeMaxDynamicSharedMemorySize, SMEM_FLASH);

    const int x4 = MTOT * DD / 4;
    const int w4 = DD * DD / 4;
    dim3 gg(DD / 128, MTOT / 128);  // (8, 32)

    convert_flat<<<x4 / 256, 256>>>(Q, 0, x4);
    convert_flat<<<w4 / 256, 256>>>(Wq, 1, w4);
    gemm_tc<0><<<gg, 256, SMEM_GEMM>>>(bq, nullptr);

    convert_flat<<<x4 / 256, 256>>>(K, 0, x4);
    convert_flat<<<w4 / 256, 256>>>(Wk, 1, w4);
    gemm_tc<1><<<gg, 256, SMEM_GEMM>>>(bk, nullptr);

    convert_flat<<<x4 / 256, 256>>>(V, 0, x4);
    convert_flat<<<w4 / 256, 256>>>(Wv, 1, w4);
    gemm_tc<2><<<gg, 256, SMEM_GEMM>>>(bv, nullptr);

    flash_mma<<<dim3(SS / 128, HH, BB), 256, SMEM_FLASH>>>();

    convert_flat<<<w4 / 256, 256>>>(Wo, 1, w4);
    gemm_tc<3><<<gg, 256, SMEM_GEMM>>>(bo, out);
}

// round 10
// speedup vs baseline: 2.3094x; 1.0998x over previous
#include <cuda_runtime.h>
#include <cuda_bf16.h>
#include <cstdint>
#include <math.h>

#define BB   2
#define SS   2048
#define DD   1024
#define HH   16
#define HDIM 64
#define MTOT (BB*SS)   // 4096

// ---------------- scratch (__device__ globals; device-side refs ONLY) ------
__device__ __align__(16) __nv_bfloat16 g_qhi[BB*HH*SS*HDIM];
__device__ __align__(16) __nv_bfloat16 g_khi[BB*HH*SS*HDIM];
__device__ __align__(16) __nv_bfloat16 g_vhi[BB*HH*SS*HDIM];
__device__ __align__(16) __nv_bfloat16 g_vlo[BB*HH*SS*HDIM];
__device__ __align__(16) __nv_bfloat16 g_xhi[MTOT*DD];
__device__ __align__(16) __nv_bfloat16 g_xlo[MTOT*DD];
__device__ __align__(16) __nv_bfloat16 g_whi[DD*DD];
__device__ __align__(16) __nv_bfloat16 g_wlo[DD*DD];

// ---------------- helpers ---------------------------------------------------
__device__ __forceinline__ void mma16816(float* c, const uint32_t* a, const uint32_t* b) {
    asm volatile(
        "mma.sync.aligned.m16n8k16.row.col.f32.bf16.bf16.f32 "
        "{%0,%1,%2,%3},{%4,%5,%6,%7},{%8,%9},{%0,%1,%2,%3};"
        : "+f"(c[0]), "+f"(c[1]), "+f"(c[2]), "+f"(c[3])
        : "r"(a[0]), "r"(a[1]), "r"(a[2]), "r"(a[3]), "r"(b[0]), "r"(b[1]));
}

__device__ __forceinline__ uint32_t pack_bf16x2(float lo, float hi) {
    uint32_t d;
    asm("cvt.rn.bf16x2.f32 %0, %1, %2;" : "=r"(d) : "f"(hi), "f"(lo));
    return d;
}
__device__ __forceinline__ void split_pair(float x, float y, uint32_t& ph, uint32_t& pl) {
    ph = pack_bf16x2(x, y);
    float tx = __uint_as_float(ph << 16);
    float ty = __uint_as_float(ph & 0xFFFF0000u);
    pl = pack_bf16x2(x - tx, y - ty);
}

// fast 2^f via FMA (no MUFU). f <= ~1, clamped at -80.
__device__ __forceinline__ float fast_exp2(float f) {
    f = fmaxf(f, -80.0f);
    float t2 = f + 12582912.0f;
    float r  = f - (t2 - 12582912.0f);
    float p  = 1.0f + r * (0.69314718f + r * (0.24022651f +
                   r * (0.05550411f + r * 0.00961813f)));
    uint32_t eb = (__float_as_uint(t2) << 23) - (0x4B400000u << 23);
    return __uint_as_float(__float_as_uint(p) + eb);
}

// ---------------- bf16 split conversion (inputs/weights) -------------------
__device__ __forceinline__ void split4(float4 v, uint2& hi, uint2& lo) {
    __nv_bfloat16 h0 = __float2bfloat16(v.x), h1 = __float2bfloat16(v.y);
    __nv_bfloat16 h2 = __float2bfloat16(v.z), h3 = __float2bfloat16(v.w);
    __nv_bfloat16 l0 = __float2bfloat16(v.x - __bfloat162float(h0));
    __nv_bfloat16 l1 = __float2bfloat16(v.y - __bfloat162float(h1));
    __nv_bfloat16 l2 = __float2bfloat16(v.z - __bfloat162float(h2));
    __nv_bfloat16 l3 = __float2bfloat16(v.w - __bfloat162float(h3));
    hi.x = ((uint32_t)__bfloat16_as_ushort(h1) << 16) | __bfloat16_as_ushort(h0);
    hi.y = ((uint32_t)__bfloat16_as_ushort(h3) << 16) | __bfloat16_as_ushort(h2);
    lo.x = ((uint32_t)__bfloat16_as_ushort(l1) << 16) | __bfloat16_as_ushort(l0);
    lo.y = ((uint32_t)__bfloat16_as_ushort(l3) << 16) | __bfloat16_as_ushort(l2);
}

__global__ __launch_bounds__(256) void convert_flat(
    const float* __restrict__ src, int which, int n4)
{
    int i = blockIdx.x * blockDim.x + threadIdx.x;
    if (i >= n4) return;
    __nv_bfloat16* __restrict__ hi = (which == 0) ? g_xhi : g_whi;
    __nv_bfloat16* __restrict__ lo = (which == 0) ? g_xlo : g_wlo;
    uint2 h, l;
    split4(((const float4*)src)[i], h, l);
    ((uint2*)hi)[i] = h;
    ((uint2*)lo)[i] = l;
}

// ---------------- HMMA GEMM (proven core): 128x128 tile, 3-pass split ------
#define ROWB 272
#define A_OFF 0
#define B_OFF (128*ROWB)
#define SMEM_GEMM (2*128*ROWB)   // 69632

template<int MODE>
__global__ __launch_bounds__(256) void gemm_tc(
    const float* __restrict__ bias, float* __restrict__ outp)
{
    extern __shared__ __align__(16) char sm[];
    const int tid = threadIdx.x, wid = tid >> 5, lid = tid & 31;
    const int n0 = blockIdx.x * 128, m0 = blockIdx.y * 128;
    const int wr = wid & 1;
    const int wc = wid >> 1;

    float acc[4][4][4] = {};

    const int cp_row = tid >> 4;
    const int cp_g   = tid & 15;

    for (int c = 0; c < 24; c++) {
        const int p  = c >> 3;
        const int kc = (c & 7) * 128;
        const __nv_bfloat16* __restrict__ As = (p < 2)  ? g_xhi : g_xlo;
        const __nv_bfloat16* __restrict__ Bs = (p == 1) ? g_wlo : g_whi;

        __syncthreads();
        #pragma unroll
        for (int i = 0; i < 8; i++) {
            int row = cp_row + i * 16;
            *(uint4*)(sm + A_OFF + row * ROWB + cp_g * 16) =
                *(const uint4*)(As + (size_t)(m0 + row) * DD + kc + cp_g * 8);
            *(uint4*)(sm + B_OFF + row * ROWB + cp_g * 16) =
                *(const uint4*)(Bs + (size_t)(n0 + row) * DD + kc + cp_g * 8);
        }
        __syncthreads();

        #pragma unroll
        for (int st = 0; st < 8; st++) {
            const int kbyte = st * 32 + (lid & 3) * 4;
            uint32_t af[4][4], bf[4][2];
            #pragma unroll
            for (int mt = 0; mt < 4; mt++) {
                const char* base = sm + A_OFF +
                    (wr * 64 + mt * 16 + (lid >> 2)) * ROWB + kbyte;
                af[mt][0] = *(const uint32_t*)(base);
                af[mt][1] = *(const uint32_t*)(base + 8 * ROWB);
                af[mt][2] = *(const uint32_t*)(base + 16);
                af[mt][3] = *(const uint32_t*)(base + 8 * ROWB + 16);
            }
            #pragma unroll
            for (int nt = 0; nt < 4; nt++) {
                const char* base = sm + B_OFF +
                    (wc * 32 + nt * 8 + (lid >> 2)) * ROWB + kbyte;
                bf[nt][0] = *(const uint32_t*)(base);
                bf[nt][1] = *(const uint32_t*)(base + 16);
            }
            #pragma unroll
            for (int mt = 0; mt < 4; mt++)
                #pragma unroll
                for (int nt = 0; nt < 4; nt++)
                    mma16816(acc[mt][nt], af[mt], bf[nt]);
        }
    }

    // epilogue. MODE 0/1 (q,k): hi only (flash QK^T is 1-pass now).
    // MODE 2 (v): hi+lo. MODE 3: fp32 out.
    #pragma unroll
    for (int mt = 0; mt < 4; mt++) {
        #pragma unroll
        for (int nt = 0; nt < 4; nt++) {
            int col = n0 + wc * 32 + nt * 8 + (lid & 3) * 2;
            float2 bv = *(const float2*)(bias + col);
            int r0 = m0 + wr * 64 + mt * 16 + (lid >> 2);
            #pragma unroll
            for (int half = 0; half < 2; half++) {
                int r = r0 + half * 8;
                float ox = acc[mt][nt][half * 2 + 0] + bv.x;
                float oy = acc[mt][nt][half * 2 + 1] + bv.y;
                if (MODE == 3) {
                    float2 o = {ox, oy};
                    *(float2*)(outp + (size_t)r * DD + col) = o;
                } else {
                    int b = r >> 11, s = r & (SS - 1);
                    int hh = col >> 6, hd = col & 63;
                    size_t off = (((size_t)(b * HH + hh)) * SS + s) * HDIM + hd;
                    uint32_t ph, pl;
                    split_pair(ox, oy, ph, pl);
                    if (MODE == 0) {
                        *(uint32_t*)(g_qhi + off) = ph;
                    } else if (MODE == 1) {
                        *(uint32_t*)(g_khi + off) = ph;
                    } else {
                        *(uint32_t*)(g_vhi + off) = ph;
                        *(uint32_t*)(g_vlo + off) = pl;
                    }
                }
            }
        }
    }
}

// ---------------- flash attention on mma.sync ------------------------------
// QK^T: 1-pass bf16 (softmax tolerates ~2^-9 absolute score noise).
// PV: 3-pass split (output-linear, needs the cross terms).
#define QROWB 144
#define VROWB 272
#define OFF_QHI 0
#define OFF_KHI 18432
#define OFF_VHI 36864
#define OFF_VLO 54272
#define OFF_PHI 71680
#define OFF_PLO 106496
#define SMEM_FLASH 141312

__device__ __forceinline__ void s_pass(
    float sf[16][4], const uint32_t a[4][4], const char* kb, int lid)
{
    #pragma unroll
    for (int nt = 0; nt < 16; nt++) {
        #pragma unroll
        for (int ks = 0; ks < 4; ks++) {
            const char* p = kb + (nt * 8 + (lid >> 2)) * QROWB + ks * 32 + (lid & 3) * 4;
            uint32_t bf[2] = { *(const uint32_t*)p, *(const uint32_t*)(p + 16) };
            mma16816(sf[nt], a[ks], bf);
        }
    }
}

__device__ __forceinline__ void pv_pass(
    float acc[8][4], const char* pbase, const char* vb, int lid)
{
    uint32_t aP[8][4];
    const int rb = (lid >> 2) * VROWB + (lid & 3) * 4;
    #pragma unroll
    for (int ks = 0; ks < 8; ks++) {
        const char* p = pbase + rb + ks * 32;
        aP[ks][0] = *(const uint32_t*)(p);
        aP[ks][1] = *(const uint32_t*)(p + 8 * VROWB);
        aP[ks][2] = *(const uint32_t*)(p + 16);
        aP[ks][3] = *(const uint32_t*)(p + 8 * VROWB + 16);
    }
    #pragma unroll
    for (int nt = 0; nt < 8; nt++) {
        #pragma unroll
        for (int ks = 0; ks < 8; ks++) {
            const char* p = vb + (nt * 8 + (lid >> 2)) * VROWB + ks * 32 + (lid & 3) * 4;
            uint32_t bf[2] = { *(const uint32_t*)p, *(const uint32_t*)(p + 16) };
            mma16816(acc[nt], aP[ks], bf);
        }
    }
}

__global__ __launch_bounds__(256, 1) void flash_mma()
{
    extern __shared__ __align__(16) char sm[];
    const int tid = threadIdx.x, wid = tid >> 5, lid = tid & 31;
    const int q0 = blockIdx.x * 128, h = blockIdx.y, b = blockIdx.z;
    const size_t base = ((size_t)(b * HH + h)) * SS * HDIM;
    const float cf = 0.18033688f;   // 0.125 * log2(e)

    // Q tile 128x64 (hi only) -> smem, full 128B rows via uint4
    #pragma unroll
    for (int i = 0; i < 4; i++) {
        int idx = tid + i * 256, row = idx >> 3, g = idx & 7;
        size_t src = base + (size_t)(q0 + row) * HDIM + g * 8;
        *(uint4*)(sm + OFF_QHI + row * QROWB + g * 16) = *(const uint4*)(g_qhi + src);
    }
    __syncthreads();

    uint32_t aQh[4][4];
    const int qrb = (wid * 16 + (lid >> 2)) * QROWB + (lid & 3) * 4;
    #pragma unroll
    for (int ks = 0; ks < 4; ks++) {
        const char* p = sm + OFF_QHI + qrb + ks * 32;
        aQh[ks][0] = *(const uint32_t*)(p);
        aQh[ks][1] = *(const uint32_t*)(p + 8 * QROWB);
        aQh[ks][2] = *(const uint32_t*)(p + 16);
        aQh[ks][3] = *(const uint32_t*)(p + 8 * QROWB + 16);
    }

    float acc[8][4] = {};
    float mrow[2] = {-1e30f, -1e30f}, lrow[2] = {0.f, 0.f};

    for (int kt0 = 0; kt0 < SS; kt0 += 128) {
        __syncthreads();

        // K chunk (hi only)
        #pragma unroll
        for (int i = 0; i < 4; i++) {
            int idx = tid + i * 256, row = idx >> 3, g = idx & 7;
            size_t src = base + (size_t)(kt0 + row) * HDIM + g * 8;
            *(uint4*)(sm + OFF_KHI + row * QROWB + g * 16) = *(const uint4*)(g_khi + src);
        }
        // V chunk transposed (hi/lo)
        #pragma unroll
        for (int i = 0; i < 8; i++) {
            int idx = tid + i * 256, kt = idx >> 4, g = idx & 15;
            size_t src = base + (size_t)(kt0 + kt) * HDIM + g * 4;
            uint2 vh = *(const uint2*)(g_vhi + src);
            uint2 vl = *(const uint2*)(g_vlo + src);
            #pragma unroll
            for (int j = 0; j < 4; j++) {
                uint16_t hv = (j < 2) ? (uint16_t)(vh.x >> (j * 16))
                                      : (uint16_t)(vh.y >> ((j - 2) * 16));
                uint16_t lv = (j < 2) ? (uint16_t)(vl.x >> (j * 16))
                                      : (uint16_t)(vl.y >> ((j - 2) * 16));
                *(uint16_t*)(sm + OFF_VHI + (g * 4 + j) * VROWB + kt * 2) = hv;
                *(uint16_t*)(sm + OFF_VLO + (g * 4 + j) * VROWB + kt * 2) = lv;
            }
        }
        __syncthreads();

        // S = Qhi Khi^T (single pass)
        float sf[16][4];
        #pragma unroll
        for (int nt = 0; nt < 16; nt++)
            sf[nt][0] = sf[nt][1] = sf[nt][2] = sf[nt][3] = 0.f;
        s_pass(sf, aQh, sm + OFF_KHI, lid);

        // online softmax
        float corr[2];
        #pragma unroll
        for (int half = 0; half < 2; half++) {
            const int v0 = half * 2, v1 = half * 2 + 1;
            float tm = -1e30f;
            #pragma unroll
            for (int nt = 0; nt < 16; nt++)
                tm = fmaxf(tm, fmaxf(sf[nt][v0], sf[nt][v1]));
            tm = fmaxf(tm, __shfl_xor_sync(0xffffffffu, tm, 1));
            tm = fmaxf(tm, __shfl_xor_sync(0xffffffffu, tm, 2));
            float mn = fmaxf(mrow[half], tm * cf);
            corr[half] = fast_exp2(mrow[half] - mn);
            mrow[half] = mn;
            float sum = 0.f;
            #pragma unroll
            for (int nt = 0; nt < 16; nt++) {
                float p0 = fast_exp2(fmaf(sf[nt][v0], cf, -mn));
                float p1 = fast_exp2(fmaf(sf[nt][v1], cf, -mn));
                sf[nt][v0] = p0; sf[nt][v1] = p1;
                sum += p0 + p1;
            }
            sum += __shfl_xor_sync(0xffffffffu, sum, 1);
            sum += __shfl_xor_sync(0xffffffffu, sum, 2);
            lrow[half] = lrow[half] * corr[half] + sum;
        }
        #pragma unroll
        for (int nt = 0; nt < 8; nt++) {
            acc[nt][0] *= corr[0]; acc[nt][1] *= corr[0];
            acc[nt][2] *= corr[1]; acc[nt][3] *= corr[1];
        }

        // store P hi/lo (own-warp strip)
        const int pr0 = (wid * 16 + (lid >> 2)) * VROWB;
        const int pcb = 4 * (lid & 3);
        #pragma unroll
        for (int nt = 0; nt < 16; nt++) {
            int cb = nt * 16 + pcb;
            uint32_t ph, pl;
            split_pair(sf[nt][0], sf[nt][1], ph, pl);
            *(uint32_t*)(sm + OFF_PHI + pr0 + cb) = ph;
            *(uint32_t*)(sm + OFF_PLO + pr0 + cb) = pl;
            split_pair(sf[nt][2], sf[nt][3], ph, pl);
            *(uint32_t*)(sm + OFF_PHI + pr0 + 8 * VROWB + cb) = ph;
            *(uint32_t*)(sm + OFF_PLO + pr0 + 8 * VROWB + cb) = pl;
        }
        __syncwarp();

        // acc += P @ V (3-pass split)
        const char* pwhi = sm + OFF_PHI + wid * 16 * VROWB;
        const char* pwlo = sm + OFF_PLO + wid * 16 * VROWB;
        pv_pass(acc, pwhi, sm + OFF_VHI, lid);
        pv_pass(acc, pwhi, sm + OFF_VLO, lid);
        pv_pass(acc, pwlo, sm + OFF_VHI, lid);
    }

    // epilogue: normalize, split, write ctx hi/lo row-major [M, D]
    float inv0 = 1.0f / lrow[0], inv1 = 1.0f / lrow[1];
    int r0 = q0 + wid * 16 + (lid >> 2);
    size_t m0 = (size_t)(b * SS + r0) * DD + h * HDIM;
    #pragma unroll
    for (int nt = 0; nt < 8; nt++) {
        int d = nt * 8 + 2 * (lid & 3);
        uint32_t ph, pl;
        split_pair(acc[nt][0] * inv0, acc[nt][1] * inv0, ph, pl);
        *(uint32_t*)(g_xhi + m0 + d) = ph;
        *(uint32_t*)(g_xlo + m0 + d) = pl;
        split_pair(acc[nt][2] * inv1, acc[nt][3] * inv1, ph, pl);
        *(uint32_t*)(g_xhi + m0 + 8 * DD + d) = ph;
        *(uint32_t*)(g_xlo + m0 + 8 * DD + d) = pl;
    }
}

// ---------------------------------------------------------------------------
extern "C" void kernel_launch(void* const* d_in, const int* in_sizes, int n_in,
                              void* d_out, int out_size)
{
    const float* Q  = (const float*)d_in[0];
    const float* K  = (const float*)d_in[1];
    const float* V  = (const float*)d_in[2];
    const float* Wq = (const float*)d_in[3];
    const float* bq = (const float*)d_in[4];
    const float* Wk = (const float*)d_in[5];
    const float* bk = (const float*)d_in[6];
    const float* Wv = (const float*)d_in[7];
    const float* bv = (const float*)d_in[8];
    const float* Wo = (const float*)d_in[9];
    const float* bo = (const float*)d_in[10];
    float* out = (float*)d_out;

    cudaFuncSetAttribute(gemm_tc<0>, cudaFuncAttributeMaxDynamicSharedMemorySize, SMEM_GEMM);
    cudaFuncSetAttribute(gemm_tc<1>, cudaFuncAttributeMaxDynamicSharedMemorySize, SMEM_GEMM);
    cudaFuncSetAttribute(gemm_tc<2>, cudaFuncAttributeMaxDynamicSharedMemorySize, SMEM_GEMM);
    cudaFuncSetAttribute(gemm_tc<3>, cudaFuncAttributeMaxDynamicSharedMemorySize, SMEM_GEMM);
    cudaFuncSetAttribute(flash_mma,  cudaFuncAttributeMaxDynamicSharedMemorySize, SMEM_FLASH);

    const int x4 = MTOT * DD / 4;
    const int w4 = DD * DD / 4;
    dim3 gg(DD / 128, MTOT / 128);  // (8, 32)

    convert_flat<<<x4 / 256, 256>>>(Q, 0, x4);
    convert_flat<<<w4 / 256, 256>>>(Wq, 1, w4);
    gemm_tc<0><<<gg, 256, SMEM_GEMM>>>(bq, nullptr);

    convert_flat<<<x4 / 256, 256>>>(K, 0, x4);
    convert_flat<<<w4 / 256, 256>>>(Wk, 1, w4);
    gemm_tc<1><<<gg, 256, SMEM_GEMM>>>(bk, nullptr);

    convert_flat<<<x4 / 256, 256>>>(V, 0, x4);
    convert_flat<<<w4 / 256, 256>>>(Wv, 1, w4);
    gemm_tc<2><<<gg, 256, SMEM_GEMM>>>(bv, nullptr);

    flash_mma<<<dim3(SS / 128, HH, BB), 256, SMEM_FLASH>>>();

    convert_flat<<<w4 / 256, 256>>>(Wo, 1, w4);
    gemm_tc<3><<<gg, 256, SMEM_GEMM>>>(bo, out);
}

// round 11
// speedup vs baseline: 2.4725x; 1.0707x over previous
#include <cuda_runtime.h>
#include <cuda_bf16.h>
#include <cstdint>
#include <math.h>

#define BB   2
#define SS   2048
#define DD   1024
#define HH   16
#define HDIM 64
#define MTOT (BB*SS)   // 4096

// ---------------- scratch (__device__ globals; device-side refs ONLY) ------
__device__ __align__(16) __nv_bfloat16 g_qhi[BB*HH*SS*HDIM];
__device__ __align__(16) __nv_bfloat16 g_khi[BB*HH*SS*HDIM];
__device__ __align__(16) __nv_bfloat16 g_vhi[BB*HH*SS*HDIM];
__device__ __align__(16) __nv_bfloat16 g_vlo[BB*HH*SS*HDIM];
__device__ __align__(16) __nv_bfloat16 g_xhi[MTOT*DD];
__device__ __align__(16) __nv_bfloat16 g_xlo[MTOT*DD];
__device__ __align__(16) __nv_bfloat16 g_whi[DD*DD];
__device__ __align__(16) __nv_bfloat16 g_wlo[DD*DD];

// ---------------- helpers ---------------------------------------------------
__device__ __forceinline__ void mma16816(float* c, const uint32_t* a, const uint32_t* b) {
    asm volatile(
        "mma.sync.aligned.m16n8k16.row.col.f32.bf16.bf16.f32 "
        "{%0,%1,%2,%3},{%4,%5,%6,%7},{%8,%9},{%0,%1,%2,%3};"
        : "+f"(c[0]), "+f"(c[1]), "+f"(c[2]), "+f"(c[3])
        : "r"(a[0]), "r"(a[1]), "r"(a[2]), "r"(a[3]), "r"(b[0]), "r"(b[1]));
}

__device__ __forceinline__ uint32_t pack_bf16x2(float lo, float hi) {
    uint32_t d;
    asm("cvt.rn.bf16x2.f32 %0, %1, %2;" : "=r"(d) : "f"(hi), "f"(lo));
    return d;
}
__device__ __forceinline__ void split_pair(float x, float y, uint32_t& ph, uint32_t& pl) {
    ph = pack_bf16x2(x, y);
    float tx = __uint_as_float(ph << 16);
    float ty = __uint_as_float(ph & 0xFFFF0000u);
    pl = pack_bf16x2(x - tx, y - ty);
}

// fast 2^f via FMA (no MUFU). f <= ~1, clamped at -80.
__device__ __forceinline__ float fast_exp2(float f) {
    f = fmaxf(f, -80.0f);
    float t2 = f + 12582912.0f;
    float r  = f - (t2 - 12582912.0f);
    float p  = 1.0f + r * (0.69314718f + r * (0.24022651f +
                   r * (0.05550411f + r * 0.00961813f)));
    uint32_t eb = (__float_as_uint(t2) << 23) - (0x4B400000u << 23);
    return __uint_as_float(__float_as_uint(p) + eb);
}

__device__ __forceinline__ uint32_t smem_u32(const void* p) {
    uint32_t a;
    asm("{ .reg .u64 t; cvta.to.shared.u64 t, %1; cvt.u32.u64 %0, t; }"
        : "=r"(a) : "l"(p));
    return a;
}
#define CP_ASYNC16(dst, src) \
    asm volatile("cp.async.cg.shared.global [%0], [%1], 16;" \
        :: "r"(dst), "l"(src) : "memory")
#define CP_COMMIT() asm volatile("cp.async.commit_group;" ::: "memory")
#define CP_WAIT0()  asm volatile("cp.async.wait_group 0;" ::: "memory")

// ---------------- bf16 split conversion (inputs/weights) -------------------
__device__ __forceinline__ void split4(float4 v, uint2& hi, uint2& lo) {
    __nv_bfloat16 h0 = __float2bfloat16(v.x), h1 = __float2bfloat16(v.y);
    __nv_bfloat16 h2 = __float2bfloat16(v.z), h3 = __float2bfloat16(v.w);
    __nv_bfloat16 l0 = __float2bfloat16(v.x - __bfloat162float(h0));
    __nv_bfloat16 l1 = __float2bfloat16(v.y - __bfloat162float(h1));
    __nv_bfloat16 l2 = __float2bfloat16(v.z - __bfloat162float(h2));
    __nv_bfloat16 l3 = __float2bfloat16(v.w - __bfloat162float(h3));
    hi.x = ((uint32_t)__bfloat16_as_ushort(h1) << 16) | __bfloat16_as_ushort(h0);
    hi.y = ((uint32_t)__bfloat16_as_ushort(h3) << 16) | __bfloat16_as_ushort(h2);
    lo.x = ((uint32_t)__bfloat16_as_ushort(l1) << 16) | __bfloat16_as_ushort(l0);
    lo.y = ((uint32_t)__bfloat16_as_ushort(l3) << 16) | __bfloat16_as_ushort(l2);
}

__global__ __launch_bounds__(256) void convert_flat(
    const float* __restrict__ src, int which, int n4)
{
    int i = blockIdx.x * blockDim.x + threadIdx.x;
    if (i >= n4) return;
    __nv_bfloat16* __restrict__ hi = (which == 0) ? g_xhi : g_whi;
    __nv_bfloat16* __restrict__ lo = (which == 0) ? g_xlo : g_wlo;
    uint2 h, l;
    split4(((const float4*)src)[i], h, l);
    ((uint2*)hi)[i] = h;
    ((uint2*)lo)[i] = l;
}

// ---------------- HMMA GEMM: 128x128 tile, 3-pass split, cp.async fills ----
#define ROWB 272
#define A_OFF 0
#define B_OFF (128*ROWB)
#define SMEM_GEMM (2*128*ROWB)   // 69632

template<int MODE>
__global__ __launch_bounds__(256) void gemm_tc(
    const float* __restrict__ bias, float* __restrict__ outp)
{
    extern __shared__ __align__(16) char sm[];
    const int tid = threadIdx.x, wid = tid >> 5, lid = tid & 31;
    const int n0 = blockIdx.x * 128, m0 = blockIdx.y * 128;
    const int wr = wid & 1;
    const int wc = wid >> 1;
    const uint32_t sb = smem_u32(sm);

    float acc[4][4][4] = {};

    const int cp_row = tid >> 4;
    const int cp_g   = tid & 15;

    for (int c = 0; c < 24; c++) {
        const int p  = c >> 3;
        const int kc = (c & 7) * 128;
        const __nv_bfloat16* __restrict__ As = (p < 2)  ? g_xhi : g_xlo;
        const __nv_bfloat16* __restrict__ Bs = (p == 1) ? g_wlo : g_whi;

        __syncthreads();
        #pragma unroll
        for (int i = 0; i < 8; i++) {
            int row = cp_row + i * 16;
            CP_ASYNC16(sb + A_OFF + row * ROWB + cp_g * 16,
                       (const void*)(As + (size_t)(m0 + row) * DD + kc + cp_g * 8));
            CP_ASYNC16(sb + B_OFF + row * ROWB + cp_g * 16,
                       (const void*)(Bs + (size_t)(n0 + row) * DD + kc + cp_g * 8));
        }
        CP_COMMIT();
        CP_WAIT0();
        __syncthreads();

        #pragma unroll
        for (int st = 0; st < 8; st++) {
            const int kbyte = st * 32 + (lid & 3) * 4;
            uint32_t af[4][4], bf[4][2];
            #pragma unroll
            for (int mt = 0; mt < 4; mt++) {
                const char* base = sm + A_OFF +
                    (wr * 64 + mt * 16 + (lid >> 2)) * ROWB + kbyte;
                af[mt][0] = *(const uint32_t*)(base);
                af[mt][1] = *(const uint32_t*)(base + 8 * ROWB);
                af[mt][2] = *(const uint32_t*)(base + 16);
                af[mt][3] = *(const uint32_t*)(base + 8 * ROWB + 16);
            }
            #pragma unroll
            for (int nt = 0; nt < 4; nt++) {
                const char* base = sm + B_OFF +
                    (wc * 32 + nt * 8 + (lid >> 2)) * ROWB + kbyte;
                bf[nt][0] = *(const uint32_t*)(base);
                bf[nt][1] = *(const uint32_t*)(base + 16);
            }
            #pragma unroll
            for (int mt = 0; mt < 4; mt++)
                #pragma unroll
                for (int nt = 0; nt < 4; nt++)
                    mma16816(acc[mt][nt], af[mt], bf[nt]);
        }
    }

    // epilogue. MODE 0/1 (q,k): hi only. MODE 2 (v): hi+lo. MODE 3: fp32 out.
    #pragma unroll
    for (int mt = 0; mt < 4; mt++) {
        #pragma unroll
        for (int nt = 0; nt < 4; nt++) {
            int col = n0 + wc * 32 + nt * 8 + (lid & 3) * 2;
            float2 bv = *(const float2*)(bias + col);
            int r0 = m0 + wr * 64 + mt * 16 + (lid >> 2);
            #pragma unroll
            for (int half = 0; half < 2; half++) {
                int r = r0 + half * 8;
                float ox = acc[mt][nt][half * 2 + 0] + bv.x;
                float oy = acc[mt][nt][half * 2 + 1] + bv.y;
                if (MODE == 3) {
                    float2 o = {ox, oy};
                    *(float2*)(outp + (size_t)r * DD + col) = o;
                } else {
                    int b = r >> 11, s = r & (SS - 1);
                    int hh = col >> 6, hd = col & 63;
                    size_t off = (((size_t)(b * HH + hh)) * SS + s) * HDIM + hd;
                    uint32_t ph, pl;
                    split_pair(ox, oy, ph, pl);
                    if (MODE == 0) {
                        *(uint32_t*)(g_qhi + off) = ph;
                    } else if (MODE == 1) {
                        *(uint32_t*)(g_khi + off) = ph;
                    } else {
                        *(uint32_t*)(g_vhi + off) = ph;
                        *(uint32_t*)(g_vlo + off) = pl;
                    }
                }
            }
        }
    }
}

// ---------------- flash attention on mma.sync ------------------------------
// QK^T: 1-pass bf16. PV: 3-pass split with P kept IN REGISTERS:
// C-fragment of S-tile nt maps exactly onto the A-fragment of PV k-chunk
// ks = nt/2  (a0,a1 = c0c1,c2c3 of nt=2ks; a2,a3 = c0c1,c2c3 of nt=2ks+1).
#define QROWB 144
#define VROWB 272
#define OFF_QHI 0
#define OFF_KHI 18432
#define OFF_VHI 36864
#define OFF_VLO 54272
#define SMEM_FLASH 71680

__device__ __forceinline__ void s_pass(
    float sf[16][4], const uint32_t a[4][4], const char* kb, int lid)
{
    #pragma unroll
    for (int nt = 0; nt < 16; nt++) {
        #pragma unroll
        for (int ks = 0; ks < 4; ks++) {
            const char* p = kb + (nt * 8 + (lid >> 2)) * QROWB + ks * 32 + (lid & 3) * 4;
            uint32_t bf[2] = { *(const uint32_t*)p, *(const uint32_t*)(p + 16) };
            mma16816(sf[nt], a[ks], bf);
        }
    }
}

__global__ __launch_bounds__(256, 1) void flash_mma()
{
    extern __shared__ __align__(16) char sm[];
    const int tid = threadIdx.x, wid = tid >> 5, lid = tid & 31;
    const int q0 = blockIdx.x * 128, h = blockIdx.y, b = blockIdx.z;
    const size_t base = ((size_t)(b * HH + h)) * SS * HDIM;
    const float cf = 0.18033688f;   // 0.125 * log2(e)

    // Q tile 128x64 (hi only) -> smem, full 128B rows via uint4
    #pragma unroll
    for (int i = 0; i < 4; i++) {
        int idx = tid + i * 256, row = idx >> 3, g = idx & 7;
        size_t src = base + (size_t)(q0 + row) * HDIM + g * 8;
        *(uint4*)(sm + OFF_QHI + row * QROWB + g * 16) = *(const uint4*)(g_qhi + src);
    }
    __syncthreads();

    uint32_t aQh[4][4];
    const int qrb = (wid * 16 + (lid >> 2)) * QROWB + (lid & 3) * 4;
    #pragma unroll
    for (int ks = 0; ks < 4; ks++) {
        const char* p = sm + OFF_QHI + qrb + ks * 32;
        aQh[ks][0] = *(const uint32_t*)(p);
        aQh[ks][1] = *(const uint32_t*)(p + 8 * QROWB);
        aQh[ks][2] = *(const uint32_t*)(p + 16);
        aQh[ks][3] = *(const uint32_t*)(p + 8 * QROWB + 16);
    }

    float acc[8][4] = {};
    float mrow[2] = {-1e30f, -1e30f}, lrow[2] = {0.f, 0.f};

    for (int kt0 = 0; kt0 < SS; kt0 += 128) {
        __syncthreads();   // all warps done reading V of previous chunk

        // K chunk (hi only)
        #pragma unroll
        for (int i = 0; i < 4; i++) {
            int idx = tid + i * 256, row = idx >> 3, g = idx & 7;
            size_t src = base + (size_t)(kt0 + row) * HDIM + g * 8;
            *(uint4*)(sm + OFF_KHI + row * QROWB + g * 16) = *(const uint4*)(g_khi + src);
        }
        // V chunk transposed (hi/lo)
        #pragma unroll
        for (int i = 0; i < 8; i++) {
            int idx = tid + i * 256, kt = idx >> 4, g = idx & 15;
            size_t src = base + (size_t)(kt0 + kt) * HDIM + g * 4;
            uint2 vh = *(const uint2*)(g_vhi + src);
            uint2 vl = *(const uint2*)(g_vlo + src);
            #pragma unroll
            for (int j = 0; j < 4; j++) {
                uint16_t hv = (j < 2) ? (uint16_t)(vh.x >> (j * 16))
                                      : (uint16_t)(vh.y >> ((j - 2) * 16));
                uint16_t lv = (j < 2) ? (uint16_t)(vl.x >> (j * 16))
                                      : (uint16_t)(vl.y >> ((j - 2) * 16));
                *(uint16_t*)(sm + OFF_VHI + (g * 4 + j) * VROWB + kt * 2) = hv;
                *(uint16_t*)(sm + OFF_VLO + (g * 4 + j) * VROWB + kt * 2) = lv;
            }
        }
        __syncthreads();

        // S = Qhi Khi^T (single pass)
        float sf[16][4];
        #pragma unroll
        for (int nt = 0; nt < 16; nt++)
            sf[nt][0] = sf[nt][1] = sf[nt][2] = sf[nt][3] = 0.f;
        s_pass(sf, aQh, sm + OFF_KHI, lid);

        // online softmax
        float corr[2];
        #pragma unroll
        for (int half = 0; half < 2; half++) {
            const int v0 = half * 2, v1 = half * 2 + 1;
            float tm = -1e30f;
            #pragma unroll
            for (int nt = 0; nt < 16; nt++)
                tm = fmaxf(tm, fmaxf(sf[nt][v0], sf[nt][v1]));
            tm = fmaxf(tm, __shfl_xor_sync(0xffffffffu, tm, 1));
            tm = fmaxf(tm, __shfl_xor_sync(0xffffffffu, tm, 2));
            float mn = fmaxf(mrow[half], tm * cf);
            corr[half] = fast_exp2(mrow[half] - mn);
            mrow[half] = mn;
            float sum = 0.f;
            #pragma unroll
            for (int nt = 0; nt < 16; nt++) {
                float p0 = fast_exp2(fmaf(sf[nt][v0], cf, -mn));
                float p1 = fast_exp2(fmaf(sf[nt][v1], cf, -mn));
                sf[nt][v0] = p0; sf[nt][v1] = p1;
                sum += p0 + p1;
            }
            sum += __shfl_xor_sync(0xffffffffu, sum, 1);
            sum += __shfl_xor_sync(0xffffffffu, sum, 2);
            lrow[half] = lrow[half] * corr[half] + sum;
        }
        #pragma unroll
        for (int nt = 0; nt < 8; nt++) {
            acc[nt][0] *= corr[0]; acc[nt][1] *= corr[0];
            acc[nt][2] *= corr[1]; acc[nt][3] *= corr[1];
        }

        // pack P straight into A-fragments (NO smem round trip):
        // a0 = (c0,c1) of nt=2ks; a1 = (c2,c3) of nt=2ks; a2/a3 = same of 2ks+1
        uint32_t aPhi[8][4], aPlo[8][4];
        #pragma unroll
        for (int ks = 0; ks < 8; ks++) {
            split_pair(sf[2*ks  ][0], sf[2*ks  ][1], aPhi[ks][0], aPlo[ks][0]);
            split_pair(sf[2*ks  ][2], sf[2*ks  ][3], aPhi[ks][1], aPlo[ks][1]);
            split_pair(sf[2*ks+1][0], sf[2*ks+1][1], aPhi[ks][2], aPlo[ks][2]);
            split_pair(sf[2*ks+1][2], sf[2*ks+1][3], aPhi[ks][3], aPlo[ks][3]);
        }

        // acc += P @ V, 3 passes; Vhi fragments loaded ONCE for both P passes
        #pragma unroll
        for (int nt = 0; nt < 8; nt++) {
            #pragma unroll
            for (int ks = 0; ks < 8; ks++) {
                const char* ph = sm + OFF_VHI +
                    (nt * 8 + (lid >> 2)) * VROWB + ks * 32 + (lid & 3) * 4;
                uint32_t bh[2] = { *(const uint32_t*)ph, *(const uint32_t*)(ph + 16) };
                mma16816(acc[nt], aPhi[ks], bh);
                mma16816(acc[nt], aPlo[ks], bh);
                const char* pl = sm + OFF_VLO +
                    (nt * 8 + (lid >> 2)) * VROWB + ks * 32 + (lid & 3) * 4;
                uint32_t bl[2] = { *(const uint32_t*)pl, *(const uint32_t*)(pl + 16) };
                mma16816(acc[nt], aPhi[ks], bl);
            }
        }
    }

    // epilogue: normalize, split, write ctx hi/lo row-major [M, D]
    float inv0 = 1.0f / lrow[0], inv1 = 1.0f / lrow[1];
    int r0 = q0 + wid * 16 + (lid >> 2);
    size_t m0 = (size_t)(b * SS + r0) * DD + h * HDIM;
    #pragma unroll
    for (int nt = 0; nt < 8; nt++) {
        int d = nt * 8 + 2 * (lid & 3);
        uint32_t ph, pl;
        split_pair(acc[nt][0] * inv0, acc[nt][1] * inv0, ph, pl);
        *(uint32_t*)(g_xhi + m0 + d) = ph;
        *(uint32_t*)(g_xlo + m0 + d) = pl;
        split_pair(acc[nt][2] * inv1, acc[nt][3] * inv1, ph, pl);
        *(uint32_t*)(g_xhi + m0 + 8 * DD + d) = ph;
        *(uint32_t*)(g_xlo + m0 + 8 * DD + d) = pl;
    }
}

// ---------------------------------------------------------------------------
extern "C" void kernel_launch(void* const* d_in, const int* in_sizes, int n_in,
                              void* d_out, int out_size)
{
    const float* Q  = (const float*)d_in[0];
    const float* K  = (const float*)d_in[1];
    const float* V  = (const float*)d_in[2];
    const float* Wq = (const float*)d_in[3];
    const float* bq = (const float*)d_in[4];
    const float* Wk = (const float*)d_in[5];
    const float* bk = (const float*)d_in[6];
    const float* Wv = (const float*)d_in[7];
    const float* bv = (const float*)d_in[8];
    const float* Wo = (const float*)d_in[9];
    const float* bo = (const float*)d_in[10];
    float* out = (float*)d_out;

    cudaFuncSetAttribute(gemm_tc<0>, cudaFuncAttributeMaxDynamicSharedMemorySize, SMEM_GEMM);
    cudaFuncSetAttribute(gemm_tc<1>, cudaFuncAttributeMaxDynamicSharedMemorySize, SMEM_GEMM);
    cudaFuncSetAttribute(gemm_tc<2>, cudaFuncAttributeMaxDynamicSharedMemorySize, SMEM_GEMM);
    cudaFuncSetAttribute(gemm_tc<3>, cudaFuncAttributeMaxDynamicSharedMemorySize, SMEM_GEMM);
    cudaFuncSetAttribute(flash_mma,  cudaFuncAttributeMaxDynamicSharedMemorySize, SMEM_FLASH);

    const int x4 = MTOT * DD / 4;
    const int w4 = DD * DD / 4;
    dim3 gg(DD / 128, MTOT / 128);  // (8, 32)

    convert_flat<<<x4 / 256, 256>>>(Q, 0, x4);
    convert_flat<<<w4 / 256, 256>>>(Wq, 1, w4);
    gemm_tc<0><<<gg, 256, SMEM_GEMM>>>(bq, nullptr);

    convert_flat<<<x4 / 256, 256>>>(K, 0, x4);
    convert_flat<<<w4 / 256, 256>>>(Wk, 1, w4);
    gemm_tc<1><<<gg, 256, SMEM_GEMM>>>(bk, nullptr);

    convert_flat<<<x4 / 256, 256>>>(V, 0, x4);
    convert_flat<<<w4 / 256, 256>>>(Wv, 1, w4);
    gemm_tc<2><<<gg, 256, SMEM_GEMM>>>(bv, nullptr);

    flash_mma<<<dim3(SS / 128, HH, BB), 256, SMEM_FLASH>>>();

    convert_flat<<<w4 / 256, 256>>>(Wo, 1, w4);
    gemm_tc<3><<<gg, 256, SMEM_GEMM>>>(bo, out);
}